// round 17
// baseline (speedup 1.0000x reference)
#include <cuda_runtime.h>

// Sineconv: out[b,l,f] = sum_{w=0}^{64} x[b, l + 2f + ((f+w)>>5)] * sines[f, l+w]
//                        + x[b, l+32] * res_kernel[f]
// sines[f,s] = amplitude[f] * sin( ((frequency[f]*19000)*2pi) * sine_range[s] + phases[f]*2pi )
//
// x factor is piecewise-constant in w over 3 ranges -> each output needs
// 3 contiguous range-sums of sines (local fp32 prefix scan) + residual.
//
// R17: fy-pipelined CTA. CTA (bx,by) runs TWO f-groups (by*16, by*16+8) over
// the SAME l-tile: sr/x loaded once (sv regs + xsh reused), Psh double-
// buffered. Straight-line code lets ptxas overlap iter-1 sines/scan with
// iter-0 epilogue, breaking the chip-wide phase lockstep that pinned every
// prior design at 7.4-7.9us. 510 CTAs, 2 barriers/CTA, scalar sine path
// (f32x2 reverted: unfused packed FMA cost 4000x accuracy for 0 speed).

#define S_TOTAL 16384
#define L_OUT   16320
#define F_N     32
#define B_N     4
#define TILE_L  64
#define FG      8               // features per iteration
#define NPP     132             // Psh row stride (16B-aligned rows)
#define XW      132             // xsh row stride (only 0..127 used)

// Accurate sinf via fp32 FMA Cody-Waite (exact internal products).
// |arg| <= ~1e5 here: total reduction error ~6e-8 rad.
__device__ __forceinline__ float acc_sinf(float a) {
    float kf = rintf(a * 0.63661977236758134f);          // 2/pi
    float r  = fmaf(-kf, 1.57079637050628662e+0f, a);    // c1 = float(pi/2)
    r        = fmaf(-kf, -4.37113900018624283e-8f, r);   // c2 = float(pi/2 - c1)
    int   q  = (int)kf;
    float r2 = r * r;
    float sp = fmaf(r2, fmaf(r2, fmaf(r2, -1.9841269841e-4f, 8.3333333333e-3f),
                             -1.6666666667e-1f), 1.0f);
    float s  = r * sp;
    float c  = fmaf(r2, fmaf(r2, fmaf(r2, fmaf(r2, 2.4801587302e-5f, -1.3888888889e-3f),
                             4.1666666667e-2f), -5.0e-1f), 1.0f);
    float v = (q & 1) ? c : s;
    return (q & 2) ? -v : v;
}

// sines + scan for feature row f into Psh row [warp] of the given buffer.
__device__ __forceinline__ void row_scan(
    float (*Psh)[NPP], int warp, int lane, int f, float4 sv,
    const float* __restrict__ phases, const float* __restrict__ amplitude,
    const float* __restrict__ frequency)
{
    const float TWO_PI = 6.28318530717958647692f;
    // Replicate reference fp32 rounding: ((freq*19000)*2pi)*sr + ph
    float w2  = __fmul_rn(__fmul_rn(frequency[f], 19000.0f), TWO_PI);
    float ph  = __fmul_rn(phases[f], TWO_PI);
    float amp = amplitude[f];

    float v0 = __fmul_rn(amp, acc_sinf(__fadd_rn(__fmul_rn(w2, sv.x), ph)));
    float v1 = __fmul_rn(amp, acc_sinf(__fadd_rn(__fmul_rn(w2, sv.y), ph)));
    float v2 = __fmul_rn(amp, acc_sinf(__fadd_rn(__fmul_rn(w2, sv.z), ph)));
    float v3 = __fmul_rn(amp, acc_sinf(__fadd_rn(__fmul_rn(w2, sv.w), ph)));
    float loc0 = v0;
    float loc1 = loc0 + v1;
    float loc2 = loc1 + v2;
    float run  = loc2 + v3;
    // exclusive scan of lane totals across the warp
    float t = run;
#pragma unroll
    for (int off = 1; off < 32; off <<= 1) {
        float n = __shfl_up_sync(0xFFFFFFFFu, t, off);
        if (lane >= off) t += n;
    }
    float excl = t - run;         // exclusive prefix before sample 4*lane
    float4 w4;
    w4.x = excl;
    w4.y = excl + loc0;
    w4.z = excl + loc1;
    w4.w = excl + loc2;
    *((float4*)&Psh[warp][4 * lane]) = w4;
    if (lane == 31) Psh[warp][128] = excl + run;   // max index read is 128
}

// epilogue for one f-group from the given Psh buffer.
__device__ __forceinline__ void epilogue(
    const float (*Psh)[NPP], const float (*xsh)[XW], int tid, int s0, int fg0,
    const float* __restrict__ res_kernel, float* __restrict__ out)
{
    const int fl = tid & 7;
    const int f  = fg0 + fl;
    const int i0 = tid >> 3;             // 0..31
    const float rk = res_kernel[f];
    const int i32 = 32 - f;
    const int i64 = 64 - f;

#pragma unroll
    for (int p = 0; p < 2; p++) {
        int i = i0 + p * 32;             // local l index, 0..63
        int l = s0 + i;                  // grid exact: l < L_OUT always
        float p0 = Psh[fl][i];
        float pa = Psh[fl][i + i32];
        float pb = Psh[fl][i + i64];
        float p3 = Psh[fl][i + 65];
        float A0 = pa - p0;              // sum sines[f, l .. l+31-f]
        float A1 = pb - pa;              // sum sines[f, l+32-f .. l+63-f]
        float A2 = p3 - pb;              // sum sines[f, l+64-f .. l+64]
        int xb = i + 2 * f;
#pragma unroll
        for (int b = 0; b < B_N; b++) {
            float r = fmaf(xsh[b][xb],     A0,
                      fmaf(xsh[b][xb + 1], A1,
                      fmaf(xsh[b][xb + 2], A2,
                           xsh[b][i + 32] * rk)));
            out[(b * L_OUT + l) * F_N + f] = r;
        }
    }
}

__global__ __launch_bounds__(256, 4) void sineconv_kernel(
    const float* __restrict__ x,          // (B, S, 1)
    const float* __restrict__ sr,         // (S,)
    const float* __restrict__ phases,     // (32,)
    const float* __restrict__ amplitude,  // (32,)
    const float* __restrict__ frequency,  // (32,)
    const float* __restrict__ res_kernel, // (32,)
    float* __restrict__ out)              // (B, L, F)
{
    __shared__ __align__(16) float Psh[2][FG][NPP];  // double-buffered prefix rows
    __shared__ __align__(16) float xsh[B_N][XW];

    const int tid  = threadIdx.x;
    const int lane = tid & 31;
    const int warp = tid >> 5;
    const int s0   = blockIdx.x * TILE_L;
    const int fgA  = blockIdx.y * 16;        // first f-group
    const int fgB  = fgA + 8;                // second f-group (same l-tile!)

    // ---- loads ONCE for both iterations ----
    // sr window: 4 samples/lane, one LDG.128 (s0+127 <= 16383 always)
    const float4 sv = ((const float4*)(sr + s0))[lane];
    // x: exactly 128 floats per batch; tid<128: one LDG.128 + STS.128
    if (tid < 128) {
        int b = tid >> 5;
        int j = tid & 31;
        float4 v = ((const float4*)(x + b * S_TOTAL + s0))[j];
        *((float4*)&xsh[b][4 * j]) = v;
    }

    // ---- iter 0: sines+scan for fgA ----
    row_scan(Psh[0], warp, lane, fgA + warp, sv, phases, amplitude, frequency);
    __syncthreads();

    // ---- iter 1 sines+scan (buffer 1) + iter 0 epilogue, straight-line:
    // ptxas interleaves the independent chains (sine FMAs / scan shfls with
    // epilogue LDS/FMA/STG), filling post-scan and post-barrier bubbles.
    row_scan(Psh[1], warp, lane, fgB + warp, sv, phases, amplitude, frequency);
    epilogue(Psh[0], xsh, tid, s0, fgA, res_kernel, out);
    __syncthreads();

    // ---- iter 1 epilogue ----
    epilogue(Psh[1], xsh, tid, s0, fgB, res_kernel, out);
}

extern "C" void kernel_launch(void* const* d_in, const int* in_sizes, int n_in,
                              void* d_out, int out_size) {
    const float* x    = (const float*)d_in[0];
    const float* sr   = (const float*)d_in[1];
    const float* ph   = (const float*)d_in[2];
    const float* amp  = (const float*)d_in[3];
    const float* freq = (const float*)d_in[4];
    const float* rk   = (const float*)d_in[5];
    float* out = (float*)d_out;

    dim3 grid(L_OUT / TILE_L, 2);   // (255, 2) = 510 CTAs, 2 f-groups each
    sineconv_kernel<<<grid, 256>>>(x, sr, ph, amp, freq, rk, out);
}